// round 3
// baseline (speedup 1.0000x reference)
#include <cuda_runtime.h>

// LDM Kalman forward: 256 sequences x 1024 sequential steps.
// One CTA (256 threads) per sequence. Woodbury form:
//   Lam_t = inv(inv(P) + C^T R^-1 C),  K = Lam_t C^T R^-1
// Steady-state freeze: covariance recursion is data-independent and
// contracting; once max|dLam_pred| < 1e-6 (mask==1), K/Lam are frozen and the
// CTA splits: warp 0 runs the mu recursion register-resident via shuffles,
// warps 1..7 stream the frozen Lambda tiles to global (bandwidth-bound).

#define T_STEPS 1024
#define NB 256
#define DX 16
#define DA 32

// output layout: mu_pred_all | mu_t_all | Lambda_pred_all | Lambda_t_all
#define BASE_MP 0ul
#define BASE_MT 4194304ul
#define BASE_LP 8388608ul
#define BASE_LT 75497472ul

__device__ __forceinline__ float frcp_acc(float x) {
    float r;
    asm("rcp.approx.f32 %0, %1;" : "=f"(r) : "f"(x));
    float e = __fmaf_rn(-x, r, 1.0f);
    r = __fmaf_rn(r, e, r);   // one Newton step -> ~full fp32 accuracy
    return r;
}

// In-place Gauss-Jordan inverse of a 16x16 SPD matrix in shared memory.
// One element per thread (tid = i*16+j). One __syncthreads per pivot stage;
// threads owning row/col k+1 publish their NEW values into ping-pong buffers.
__device__ __forceinline__ void gj16(float (*M)[17], float (*rb)[DX],
                                     float (*cb)[DX], float* spv,
                                     int i, int j) {
    #pragma unroll
    for (int k = 0; k < DX; ++k) {
        const int par = k & 1, nx = par ^ 1;
        const float pr = frcp_acc(spv[par]);
        const float rk = rb[par][j];   // old M[k][j]
        const float ck = cb[par][i];   // old M[i][k]
        const float v  = M[i][j];
        float nv;
        if (i == k)      nv = (j == k) ? pr : rk * pr;
        else if (j == k) nv = -ck * pr;
        else             nv = __fmaf_rn(-(ck * pr), rk, v);
        M[i][j] = nv;
        if (k < DX - 1) {
            if (i == k + 1) rb[nx][j] = nv;
            if (j == k + 1) cb[nx][i] = nv;
            if (i == k + 1 && j == k + 1) spv[nx] = nv;
        }
        __syncthreads();
    }
}

__global__ __launch_bounds__(256, 2)
void ldm_kernel(const float* __restrict__ ga,   // [NB][T][DA]
                const float* __restrict__ gu,   // [NB][T][DX]
                const float* __restrict__ gmask,// [NB][T][1]
                const float* __restrict__ gA,   // [DX][DX]
                const float* __restrict__ gB,   // [DX][DX]
                const float* __restrict__ gC,   // [DA][DX]
                const float* __restrict__ gmu0, // [DX]
                const float* __restrict__ gLam0,// [DX][DX]
                const float* __restrict__ gWlog,// [DX]
                const float* __restrict__ gRlog,// [DA]
                float* __restrict__ out) {
    __shared__ float sA[DX][17], sB[DX][17], sCtRinvC[DX][17];
    __shared__ float sC[DA][17];
    __shared__ float sCtRinv[DX][33], sK[DX][33];
    __shared__ float sM[DX][17], sT[DX][17], sLt[DX][17], sKC[DX][17];
    __shared__ float sP[2][DX][17];
    __shared__ float rb[2][DX], cb[2][DX], spv[2];
    __shared__ float s_rinv[DA], sW[DX];
    __shared__ float s_mu[DX], s_mut[DX], s_r[DA], s_u[DX];
    __shared__ __align__(16) float sPflat[256];
    __shared__ __align__(16) float sLtflat[256];
    __shared__ float s_m;
    __shared__ int sFlag;

    const int tid = threadIdx.x;
    const int i = tid >> 4, j = tid & 15;
    const int b = blockIdx.x;

    // ---------------- constants ----------------
    sA[i][j] = gA[tid];
    sB[i][j] = gB[tid];
    for (int idx = tid; idx < DA * DX; idx += 256) sC[idx >> 4][idx & 15] = gC[idx];
    if (tid < DA) s_rinv[tid] = __expf(-gRlog[tid]);
    if (tid < DX) { sW[tid] = __expf(gWlog[tid]); s_mu[tid] = gmu0[tid]; }
    sP[0][i][j] = gLam0[tid];
    __syncthreads();
    for (int idx = tid; idx < DX * DA; idx += 256) {
        int x = idx >> 5, aa = idx & 31;
        sCtRinv[x][aa] = sC[aa][x] * s_rinv[aa];
    }
    __syncthreads();
    {
        float acc = 0.f;
        #pragma unroll
        for (int aa = 0; aa < DA; ++aa) acc = fmaf(sCtRinv[i][aa], sC[aa][j], acc);
        sCtRinvC[i][j] = acc;
    }
    __syncthreads();

    int cur = 0;
    int t_frozen = T_STEPS;  // sentinel: never froze

    // ---------------- main recursion ----------------
    for (int t = 0; t < T_STEPS; ++t) {
        if (tid == 0) { s_m = gmask[(size_t)b * T_STEPS + t]; sFlag = 0; }
        __syncthreads();
        const float m = s_m;
        const bool m1 = (m == 1.0f);

        // P -> workspace, init GJ buffers
        {
            float v = sP[cur][i][j];
            sM[i][j] = v;
            if (i == 0) rb[0][j] = v;
            if (j == 0) cb[0][i] = v;
            if (tid == 0) spv[0] = v;
        }
        __syncthreads();
        gj16(sM, rb, cb, spv, i, j);                 // sM = P^-1

        {
            float nv = sM[i][j] + sCtRinvC[i][j];
            sM[i][j] = nv;
            if (i == 0) rb[0][j] = nv;
            if (j == 0) cb[0][i] = nv;
            if (tid == 0) spv[0] = nv;
        }
        __syncthreads();
        gj16(sM, rb, cb, spv, i, j);                 // sM = Lam_t (info form)

        // K = Lam_t @ CtRinv ; T1 = A @ Lam_t ; Lt copy (mask==1 path)
        {
            #pragma unroll
            for (int rep = 0; rep < 2; ++rep) {
                int idx = tid + rep * 256;
                int ri = idx >> 5, ca = idx & 31;
                float acc = 0.f;
                #pragma unroll
                for (int y = 0; y < DX; ++y) acc = fmaf(sM[ri][y], sCtRinv[y][ca], acc);
                sK[ri][ca] = acc;
            }
            float acc = 0.f;
            #pragma unroll
            for (int k = 0; k < DX; ++k) acc = fmaf(sA[i][k], sM[k][j], acc);
            sT[i][j] = acc;
            if (m1) sLt[i][j] = sM[i][j];
        }
        __syncthreads();
        if (!m1) {  // exact general-mask path: Lt = P - m*(K C)P ; T1 = A@Lt
            float acc = 0.f;
            #pragma unroll
            for (int aa = 0; aa < DA; ++aa) acc = fmaf(sK[i][aa], sC[aa][j], acc);
            sKC[i][j] = acc;
            __syncthreads();
            float acc2 = 0.f;
            #pragma unroll
            for (int k = 0; k < DX; ++k) acc2 = fmaf(sKC[i][k], sP[cur][k][j], acc2);
            sLt[i][j] = sP[cur][i][j] - m * acc2;
            __syncthreads();
            float acc3 = 0.f;
            #pragma unroll
            for (int k = 0; k < DX; ++k) acc3 = fmaf(sA[i][k], sLt[k][j], acc3);
            sT[i][j] = acc3;
            __syncthreads();
        }

        const int nxt = cur ^ 1;
        {
            // Lam_pred' = T1 @ A^T + diag(W)
            float acc = (i == j) ? sW[i] : 0.f;
            #pragma unroll
            for (int k = 0; k < DX; ++k) acc = fmaf(sT[i][k], sA[j][k], acc);
            sP[nxt][i][j] = acc;
            if (fabsf(acc - sP[cur][i][j]) > 1e-6f) sFlag = 1;
            size_t off = ((size_t)t * NB + b) * 256 + tid;
            out[BASE_LP + off] = acc;
            out[BASE_LT + off] = sLt[i][j];
            // overlap: residual + control input
            if (tid < DA) {
                float ap = 0.f;
                #pragma unroll
                for (int k = 0; k < DX; ++k) ap = fmaf(sC[tid][k], s_mu[k], ap);
                s_r[tid] = m * ga[((size_t)b * T_STEPS + t) * DA + tid] - ap;
            } else if (tid < DA + DX) {
                int kk = tid - DA;
                s_u[kk] = (t == T_STEPS - 1) ? 0.f
                                             : gu[((size_t)b * T_STEPS + t) * DX + kk];
            }
        }
        __syncthreads();
        if (tid < DX) {
            float acc = 0.f;
            #pragma unroll
            for (int aa = 0; aa < DA; ++aa) acc = fmaf(sK[tid][aa], s_r[aa], acc);
            float mt = s_mu[tid] + m * acc;
            s_mut[tid] = mt;
            out[BASE_MT + ((size_t)t * NB + b) * DX + tid] = mt;
        }
        __syncthreads();
        if (tid < DX) {
            float acc = 0.f;
            #pragma unroll
            for (int k = 0; k < DX; ++k) acc = fmaf(sA[tid][k], s_mut[k], acc);
            #pragma unroll
            for (int k = 0; k < DX; ++k) acc = fmaf(sB[tid][k], s_u[k], acc);
            s_mu[tid] = acc;
            out[BASE_MP + ((size_t)t * NB + b) * DX + tid] = acc;
        }
        const bool conv = m1 && (sFlag == 0);
        __syncthreads();
        cur = nxt;
        if (conv) { t_frozen = t; break; }
    }

    // ---------------- post-freeze fast path ----------------
    if (t_frozen < T_STEPS - 1) {
        sPflat[tid]  = sP[cur][i][j];   // frozen Lam_pred
        sLtflat[tid] = sLt[i][j];       // frozen Lam_t
        __syncthreads();
        const int warp = tid >> 5, lane = tid & 31;
        const int t0 = t_frozen + 1;
        if (warp == 0) {
            // register-resident mu recursion, warp-synchronous
            const int lr = lane & 15;
            float Crow[DX], Arow[DX], Brow[DX], Krow[DA];
            #pragma unroll
            for (int k = 0; k < DX; ++k) Crow[k] = sC[lane][k];
            #pragma unroll
            for (int k = 0; k < DX; ++k) Arow[k] = sA[lr][k];
            #pragma unroll
            for (int k = 0; k < DX; ++k) Brow[k] = sB[lr][k];
            #pragma unroll
            for (int aa = 0; aa < DA; ++aa) Krow[aa] = sK[lr][aa];
            float mu = s_mu[lr];
            for (int t = t0; t < T_STEPS; ++t) {
                float m  = __ldg(&gmask[(size_t)b * T_STEPS + t]);
                float av = __ldg(&ga[((size_t)b * T_STEPS + t) * DA + lane]);
                float ap0 = 0.f, ap1 = 0.f;
                #pragma unroll
                for (int k = 0; k < DX; k += 2) {
                    ap0 = fmaf(Crow[k],     __shfl_sync(0xffffffffu, mu, k),     ap0);
                    ap1 = fmaf(Crow[k + 1], __shfl_sync(0xffffffffu, mu, k + 1), ap1);
                }
                float r = fmaf(m, av, -(ap0 + ap1));
                float k0 = 0.f, k1 = 0.f, k2 = 0.f, k3 = 0.f;
                #pragma unroll
                for (int aa = 0; aa < DA; aa += 4) {
                    k0 = fmaf(Krow[aa],     __shfl_sync(0xffffffffu, r, aa),     k0);
                    k1 = fmaf(Krow[aa + 1], __shfl_sync(0xffffffffu, r, aa + 1), k1);
                    k2 = fmaf(Krow[aa + 2], __shfl_sync(0xffffffffu, r, aa + 2), k2);
                    k3 = fmaf(Krow[aa + 3], __shfl_sync(0xffffffffu, r, aa + 3), k3);
                }
                float mt = fmaf(m, (k0 + k1) + (k2 + k3), mu);
                if (lane < DX) out[BASE_MT + ((size_t)t * NB + b) * DX + lane] = mt;
                float uv = 0.f;
                if (lane < DX && t < T_STEPS - 1)
                    uv = __ldg(&gu[((size_t)b * T_STEPS + t) * DX + lane]);
                float a0 = 0.f, a1 = 0.f;
                #pragma unroll
                for (int k = 0; k < DX; ++k) {
                    a0 = fmaf(Arow[k], __shfl_sync(0xffffffffu, mt, k), a0);
                    a1 = fmaf(Brow[k], __shfl_sync(0xffffffffu, uv, k), a1);
                }
                float mun = a0 + a1;
                if (lane < DX) out[BASE_MP + ((size_t)t * NB + b) * DX + lane] = mun;
                mu = mun;
            }
        } else {
            // warps 1..7: stream frozen Lambda tiles (pure STG bandwidth)
            const float4* pf = (const float4*)sPflat;
            const float4* lf = (const float4*)sLtflat;
            float4 p0 = pf[2 * lane], p1 = pf[2 * lane + 1];
            float4 l0 = lf[2 * lane], l1 = lf[2 * lane + 1];
            for (int tt = t0 + (warp - 1); tt < T_STEPS; tt += 7) {
                size_t off = ((size_t)tt * NB + b) * 256 + lane * 8;
                float4* o1 = (float4*)(out + BASE_LP + off);
                o1[0] = p0; o1[1] = p1;
                float4* o2 = (float4*)(out + BASE_LT + off);
                o2[0] = l0; o2[1] = l1;
            }
        }
    }
}

extern "C" void kernel_launch(void* const* d_in, const int* in_sizes, int n_in,
                              void* d_out, int out_size) {
    (void)in_sizes; (void)n_in; (void)out_size;
    ldm_kernel<<<NB, 256>>>(
        (const float*)d_in[0], (const float*)d_in[1], (const float*)d_in[2],
        (const float*)d_in[3], (const float*)d_in[4], (const float*)d_in[5],
        (const float*)d_in[6], (const float*)d_in[7], (const float*)d_in[8],
        (const float*)d_in[9], (float*)d_out);
}